// round 11
// baseline (speedup 1.0000x reference)
#include <cuda_runtime.h>
#include <math.h>

// BM3D-deblurring: RI filter + global empirical Wiener, Fourier domain.
// v10: = v9 + (a) g_PSD removed, psd computed from RI in-register;
// (b) row_fused syncs narrowed to pair-scoped named barriers (bar.sync id,128)
// with a pair-local Wiener loop — the two slot pairs of a block no longer
// stall on each other, and the legacy rows path only delays its own pair.

#define MAXPLANES 12
#define INVN (1.0f / 1048576.0f)
#define PHYS(p) ((p) + (((p) >> 6) << 2))   // pad 4 float2 per 64
#define FSTR 1090                           // per-FFT smem stride; 2*FSTR%32==4

static __device__ float2 g_Z[(size_t)MAXPLANES << 20]; // 96 MB packed spectra
static __device__ float2 g_Pc[1024][32];               // compact OTF scratch
static __device__ float2 g_RI[1u << 20];               // RI filter (stored layout)
static __device__ float2 g_tw[1024];                   // W_1024^k

#define PAIR_BAR(id) asm volatile("bar.sync %0, %1;" :: "r"(id), "r"(128) : "memory")

__device__ __forceinline__ int dr4(int i) {            // base-4 digit reversal
    unsigned x = __brev((unsigned)i) >> 22;
    return (int)(((x & 0x155u) << 1) | ((x & 0x2AAu) >> 1));
}
__device__ __forceinline__ float2 cadd(float2 a, float2 b){ return make_float2(a.x+b.x, a.y+b.y); }
__device__ __forceinline__ float2 csub(float2 a, float2 b){ return make_float2(a.x-b.x, a.y-b.y); }
__device__ __forceinline__ float2 cmul(float2 a, float2 b){ return make_float2(a.x*b.x-a.y*b.y, a.x*b.y+a.y*b.x); }
__device__ __forceinline__ float2 cmulj(float2 a, float2 w){ return make_float2(a.x*w.x+a.y*w.y, a.y*w.x-a.x*w.y); }

__device__ __forceinline__ void bf_dif(float2&x0, float2&x1, float2&x2, float2&x3, int e) {
    float2 t0=cadd(x0,x2), t1=csub(x0,x2), t2=cadd(x1,x3), t3=csub(x1,x3);
    float2 u1=make_float2(t1.x+t3.y, t1.y-t3.x);
    float2 u3=make_float2(t1.x-t3.y, t1.y+t3.x);
    x0=cadd(t0,t2);
    float2 u2=csub(t0,t2);
    x1=cmul(u1,g_tw[e]); x2=cmul(u2,g_tw[2*e]); x3=cmul(u3,g_tw[3*e]);
}
__device__ __forceinline__ void bf_dit(float2&x0, float2&x1, float2&x2, float2&x3, int e) {
    float2 a1=cmulj(x1,g_tw[e]), a2=cmulj(x2,g_tw[2*e]), a3=cmulj(x3,g_tw[3*e]);
    float2 t0=cadd(x0,a2), t1=csub(x0,a2), t2=cadd(a1,a3), t3=csub(a1,a3);
    x0=cadd(t0,t2);
    x1=make_float2(t1.x-t3.y, t1.y+t3.x);
    x2=csub(t0,t2);
    x3=make_float2(t1.x+t3.y, t1.y-t3.x);
}

__device__ __forceinline__ void dif_A(float2* x, int t) {
    #pragma unroll
    for (int k0=0;k0<4;k0++) bf_dif(x[k0],x[k0+4],x[k0+8],x[k0+12], t+64*k0);
    #pragma unroll
    for (int k0=0;k0<16;k0+=4) bf_dif(x[k0],x[k0+1],x[k0+2],x[k0+3], 4*t);
}
__device__ __forceinline__ void dif_B(float2* x, int e) {
    #pragma unroll
    for (int b=0;b<4;b++) bf_dif(x[b],x[4+b],x[8+b],x[12+b], (4*b+e)<<4);
    #pragma unroll
    for (int a=0;a<4;a++) bf_dif(x[4*a],x[4*a+1],x[4*a+2],x[4*a+3], e<<6);
}
__device__ __forceinline__ void dit_B(float2* x, int eh) {
    #pragma unroll
    for (int a=0;a<4;a++) bf_dit(x[4*a],x[4*a+1],x[4*a+2],x[4*a+3], eh<<6);
    #pragma unroll
    for (int b=0;b<4;b++) bf_dit(x[b],x[4+b],x[8+b],x[12+b], (4*b+eh)<<4);
}
__device__ __forceinline__ void dit_A(float2* x, int t) {
    #pragma unroll
    for (int k0=0;k0<16;k0+=4) bf_dit(x[k0],x[k0+1],x[k0+2],x[k0+3], t<<2);
    #pragma unroll
    for (int k0=0;k0<4;k0++) bf_dit(x[k0],x[k0+4],x[k0+8],x[k0+12], t+64*k0);
}

__device__ __forceinline__ float2 shx(float2 v, int m) {
    return make_float2(__shfl_xor_sync(0xffffffffu, v.x, m),
                       __shfl_xor_sync(0xffffffffu, v.y, m));
}
template <int M1, int M2>
__device__ __forceinline__ float2 difC(float2 v, int e) {
    float2 p = shx(v, M2);
    float2 A = ((e & 2) == 0) ? cadd(v, p) : csub(p, v);
    float2 q = shx(A, M1);
    if (e == 0) return cadd(A, q);
    if (e == 1) return csub(q, A);
    if (e == 2) return make_float2(A.x + q.y, A.y - q.x);
    return make_float2(q.x - A.y, q.y + A.x);
}
template <int M1, int M2>
__device__ __forceinline__ float2 ditC(float2 v, int e) {
    float2 p = shx(v, M2);
    float2 A = ((e & 2) == 0) ? cadd(v, p) : csub(p, v);
    float2 q = shx(A, M1);
    if (e == 0) return cadd(A, q);
    if (e == 1) return csub(q, A);
    if (e == 2) return make_float2(A.x - q.y, A.y + q.x);
    return make_float2(q.x + A.y, q.y - A.x);
}

// ---------------- init: twiddles only ------------------------------------
__global__ void k_init() {
    int idx = blockIdx.x * 256 + threadIdx.x;
    if (idx < 1024) {
        float sn, cs;
        sincospif(-(float)idx / 512.0f, &sn, &cs);
        g_tw[idx] = make_float2(cs, sn);
    }
}

// ---------------- prep: column DIF on the 32-col nonzero PSF band -------
__global__ void __launch_bounds__(512) k_colP_fast(const float* __restrict__ psf, int kh) {
    extern __shared__ float2 sb[];
    int tid = threadIdx.x;
    int f = tid & 7, t = tid >> 3;
    int m = t >> 2, e = t & 3;
    int bx = blockIdx.x;
    int c = (bx < 2) ? (bx * 8 + f) : (1008 + (bx - 2) * 8 + f);
    int cidx = c & 31;
    int kh2 = kh >> 1;
    int j = (c + kh2) & 1023;
    float2* buf = sb + f * FSTR;
    float2 x[16];
    #pragma unroll
    for (int k=0;k<16;k++) x[k] = make_float2(0.f, 0.f);
    if (j < kh) {
        int i0 = t + kh2;
        if (i0 < kh) x[0].x = psf[i0 * kh + j];
        int i15 = t - (64 - kh2);
        if (i15 >= 0) x[15].x = psf[i15 * kh + j];
    }
    dif_A(x, t);
    #pragma unroll
    for (int k=0;k<16;k++) buf[PHYS(t+64*k)] = x[k];
    __syncthreads();
    #pragma unroll
    for (int jj=0;jj<16;jj++){ int a=jj>>2,b=jj&3; x[jj]=buf[PHYS(64*m+16*a+4*b+e)]; }
    dif_B(x, e);
    int pe = ((e & 1) << 1) | ((e >> 1) & 1);
    #pragma unroll
    for (int jj=0;jj<16;jj++){
        int a=jj>>2, b=jj&3;
        g_Pc[64*m+16*a+4*b+pe][cidx] = difC<8, 16>(x[jj], e);
    }
}

// ---------------- prep: row DIF (32 nonzero cols) + RI ------------------
__global__ void __launch_bounds__(512) k_rowP_ri_fast() {
    extern __shared__ float2 sb[];
    int tid = threadIdx.x;
    int f = tid >> 6, t = tid & 63;
    int m = t >> 2, e = t & 3;
    int row = blockIdx.x * 8 + f;
    float2* buf = sb + f * FSTR;
    size_t gb = (size_t)row << 10;
    float2 x[16];
    #pragma unroll
    for (int k=0;k<16;k++) x[k] = make_float2(0.f, 0.f);
    if (t < 16) x[0]  = g_Pc[row][t];
    if (t >= 48) x[15] = g_Pc[row][(t + 960) & 31];
    dif_A(x, t);
    #pragma unroll
    for (int k=0;k<16;k++) buf[PHYS(t+64*k)] = x[k];
    __syncthreads();
    #pragma unroll
    for (int j=0;j<16;j++){ int a=j>>2,b=j&3; x[j]=buf[PHYS(64*m+16*a+4*b+e)]; }
    dif_B(x, e);
    int pe = ((e & 1) << 1) | ((e >> 1) & 1);
    #pragma unroll
    for (int j=0;j<16;j++){
        int a=j>>2, b=j&3;
        float2 h = difC<1, 2>(x[j], e);
        int P = 64*m+16*a+4*b+pe;
        float d = h.x*h.x + h.y*h.y + 0.0025f;
        float inv = 1.0f / d;
        g_RI[gb + P] = make_float2(h.x*inv, -h.y*inv);
    }
}

// ---------------- Wiener on a conjugate-mirror pair (psd from RI) --------
__device__ __forceinline__ void wiener_pair(float2 z1, float2 z2, int gi,
                                            float2& v1, float2& v2) {
    float2 za = make_float2(0.5f*(z1.x+z2.x), 0.5f*(z1.y-z2.y));
    float2 zb = make_float2(0.5f*(z1.y+z2.y), 0.5f*(z2.x-z1.x));
    float2 ri = g_RI[gi];
    float  pp = 0.0025f * (ri.x*ri.x + ri.y*ri.y) * 1048576.0f;  // sigma^2*|ri|^2*N
    float2 a = cmul(za, ri);
    float2 b = cmul(zb, ri);
    float Sa = fmaxf((a.x*a.x + a.y*a.y)*INVN - pp, 0.f);
    float Sb = fmaxf((b.x*b.x + b.y*b.y)*INVN - pp, 0.f);
    float wa = Sa / (Sa + pp + 1e-12f);
    float wb = Sb / (Sb + pp + 1e-12f);
    a.x*=wa; a.y*=wa; b.x*=wb; b.y*=wb;
    v1 = make_float2(a.x - b.y, a.y + b.x);
    v2 = make_float2(a.x + b.y, b.x - a.y);
}

// ---------------- pass 1: pack two real images, column DIF (8 cols) -----
__global__ void __launch_bounds__(512) k_col_fwd(const float* __restrict__ y) {
    extern __shared__ float2 sb[];
    int tid = threadIdx.x;
    int f = tid & 7, t = tid >> 3;
    int m = t >> 2, e = t & 3;
    size_t pb = (size_t)blockIdx.y << 20;
    const float* ya = y + (pb << 1);
    const float* yb = ya + (1u << 20);
    int c = (blockIdx.x << 3) + f;
    float2* buf = sb + f * FSTR;
    float2 x[16];
    #pragma unroll
    for (int k=0;k<16;k++){ int r=t+64*k; x[k]=make_float2(ya[(r<<10)+c], yb[(r<<10)+c]); }
    dif_A(x, t);
    #pragma unroll
    for (int k=0;k<16;k++) buf[PHYS(t+64*k)] = x[k];
    __syncthreads();
    #pragma unroll
    for (int j=0;j<16;j++){ int a=j>>2,b=j&3; x[j]=buf[PHYS(64*m+16*a+4*b+e)]; }
    dif_B(x, e);
    int pe = ((e & 1) << 1) | ((e >> 1) & 1);
    #pragma unroll
    for (int j=0;j<16;j++){
        int a=j>>2, b=j&3;
        float2 r = difC<8, 16>(x[j], e);
        g_Z[pb + ((size_t)(64*m+16*a+4*b+pe) << 10) + c] = r;
    }
}

// ---------------- pass 2: row DIF + ALIGNED Wiener + row DIT -------------
// Slot pairs (128 contiguous threads) are fully independent: all SMEM
// dependencies stay inside a pair, so syncs use pair-scoped named barriers.
// Odd slots compute conj(DIF(conj(.))); partner sits at the same position.
__global__ void __launch_bounds__(256) k_row_fused() {
    __shared__ float2 sb[4 * FSTR];
    int tid = threadIdx.x;
    int f = tid >> 6, t = tid & 63;
    int m = t >> 2, e = t & 3;
    int pe = ((e & 1) << 1) | ((e >> 1) & 1);
    int pr = f >> 1, h = f & 1;                        // pair index, parity
    int bid = pr + 1;                                  // named barrier id (1,2)
    int bx = blockIdx.x;
    size_t pb = (size_t)(gridDim.y - 1 - blockIdx.y) << 20;   // reverse order
    int U = 2 * bx + pr;
    int row = (U == 0) ? (h ? 2 : 0) : dr4(h ? 1024 - U : U);
    bool legacy = (bx == 0 && pr == 0);                // rows {0,512}
    bool cj = (h == 1) && !legacy;                     // conjugate-trick slot
    float2* buf = sb + f * FSTR;
    size_t gbase = pb + ((size_t)row << 10);
    float2 x[16];
    #pragma unroll
    for (int k=0;k<16;k++){
        x[k] = g_Z[gbase + t + 64*k];
        if (cj) x[k].y = -x[k].y;
    }
    dif_A(x, t);
    #pragma unroll
    for (int k=0;k<16;k++) buf[PHYS(t+64*k)] = x[k];
    PAIR_BAR(bid);                                     // S1 (pair scope)
    #pragma unroll
    for (int j=0;j<16;j++){ int a=j>>2,b=j&3; x[j]=buf[PHYS(64*m+16*a+4*b+e)]; }
    dif_B(x, e);
    // no sync: C-writes hit positions whose B-readers are in-quad
    #pragma unroll
    for (int j=0;j<16;j++){
        int a=j>>2, b=j&3;
        float2 v = difC<1, 2>(x[j], e);
        if (cj) v.y = -v.y;
        buf[PHYS(64*m+16*a+4*b+pe)] = v;
    }
    PAIR_BAR(bid);                                     // S3 (pair scope)
    // ---- pair-local aligned Wiener ----
    {
        int lt = tid & 127;
        float2* ev = sb + (2*pr) * FSTR;
        float2* od = ev + FSTR;
        if (!legacy) {
            int rA = dr4(U);
            for (int l = lt; l < 1024; l += 128) {
                float2 v1, v2;
                wiener_pair(ev[PHYS(l)], od[PHYS(l)], (rA << 10) + l, v1, v2);
                ev[PHYS(l)] = v1;
                od[PHYS(l)] = v2;
            }
        } else {                                       // rows {0,512}: self-mirrored
            for (int l = lt; l < 1026; l += 128) {
                int rw = (l >= 513); int cf = l - 513 * rw;
                int sc = dr4(cf), smc = dr4((1024 - cf) & 1023);
                float2 v1, v2;
                int rA = rw ? 2 : 0;
                float2* s0 = rw ? od : ev;
                wiener_pair(s0[PHYS(sc)], s0[PHYS(smc)], (rA << 10) + sc, v1, v2);
                s0[PHYS(sc)]  = v1;
                s0[PHYS(smc)] = v2;
            }
        }
    }
    PAIR_BAR(bid);                                     // S4 (pair scope)
    #pragma unroll
    for (int j=0;j<16;j++){
        int a=j>>2, b=j&3;
        float2 v = buf[PHYS(64*m+16*a+4*b+e)];
        if (cj) v.y = -v.y;
        x[j] = ditC<1, 2>(v, e);
    }
    dit_B(x, pe);
    // no sync: pe-writes hit positions whose e-readers are in-quad
    #pragma unroll
    for (int j=0;j<16;j++){ int a=j>>2,b=j&3; buf[PHYS(64*m+16*a+4*b+pe)] = x[j]; }
    PAIR_BAR(bid);                                     // S6 (pair scope)
    #pragma unroll
    for (int k=0;k<16;k++) x[k] = buf[PHYS(t+64*k)];
    dit_A(x, t);
    #pragma unroll
    for (int k=0;k<16;k++){
        float2 v = x[k];
        if (cj) v.y = -v.y;
        g_Z[gbase + t + 64*k] = v;
    }
}

// ---------------- pass 3: column DIT + unpack real/imag (8 cols) --------
__global__ void __launch_bounds__(512) k_col_inv(float* __restrict__ out) {
    extern __shared__ float2 sb[];
    int tid = threadIdx.x;
    int f = tid & 7, t = tid >> 3;
    int m = t >> 2, e = t & 3;
    size_t pb = (size_t)blockIdx.y << 20;
    float* oa = out + (pb << 1);
    float* ob = oa + (1u << 20);
    int c = (blockIdx.x << 3) + f;
    float2* buf = sb + f * FSTR;
    float2 x[16];
    #pragma unroll
    for (int j=0;j<16;j++){
        int a=j>>2, b=j&3;
        float2 v = g_Z[pb + ((size_t)(64*m+16*a+4*b+e) << 10) + c];
        x[j] = ditC<8, 16>(v, e);
    }
    int pe = ((e & 1) << 1) | ((e >> 1) & 1);
    dit_B(x, pe);
    #pragma unroll
    for (int j=0;j<16;j++){ int a=j>>2,b=j&3; buf[PHYS(64*m+16*a+4*b+pe)] = x[j]; }
    __syncthreads();
    #pragma unroll
    for (int k=0;k<16;k++) x[k] = buf[PHYS(t+64*k)];
    dit_A(x, t);
    #pragma unroll
    for (int k=0;k<16;k++){
        int r = t + 64*k;
        oa[(r<<10)+c] = x[k].x * INVN;
        ob[(r<<10)+c] = x[k].y * INVN;
    }
}

extern "C" void kernel_launch(void* const* d_in, const int* in_sizes, int n_in,
                              void* d_out, int out_size) {
    const float* y   = (const float*)d_in[0];
    const float* psf = (const float*)d_in[1];
    float* out = (float*)d_out;

    int imgs = in_sizes[0] >> 20;                      // 24
    int planes = imgs >> 1;                            // 12 packed complex planes
    if (planes > MAXPLANES) planes = MAXPLANES;
    int kh = (int)lroundf(sqrtf((float)in_sizes[1])); // 25

    const int colSmem = 8 * FSTR * (int)sizeof(float2);   // ~68 KB dynamic
    cudaFuncSetAttribute(k_colP_fast,    cudaFuncAttributeMaxDynamicSharedMemorySize, colSmem);
    cudaFuncSetAttribute(k_rowP_ri_fast, cudaFuncAttributeMaxDynamicSharedMemorySize, colSmem);
    cudaFuncSetAttribute(k_col_fwd,      cudaFuncAttributeMaxDynamicSharedMemorySize, colSmem);
    cudaFuncSetAttribute(k_col_inv,      cudaFuncAttributeMaxDynamicSharedMemorySize, colSmem);

    // OTF -> RI (compact band; stored digit-reversed layout)
    k_init<<<4, 256>>>();
    k_colP_fast<<<4, 512, colSmem>>>(psf, kh);
    k_rowP_ri_fast<<<128, 512, colSmem>>>();

    // main: col DIF -> fused(row DIF, aligned Wiener, row DIT) -> col DIT
    k_col_fwd<<<dim3(128, planes), 512, colSmem>>>(y);
    k_row_fused<<<dim3(256, planes), 256>>>();
    k_col_inv<<<dim3(128, planes), 512, colSmem>>>(out);
}

// round 14
// speedup vs baseline: 1.0374x; 1.0374x over previous
#include <cuda_runtime.h>
#include <math.h>

// BM3D-deblurring: RI filter + global empirical Wiener, Fourier domain.
// v11 (2nd resubmit — rounds 12 and 13 both died to infra errors at device/
// container acquisition; this source has never been benched):
// = v9 sync topology (block-wide __syncthreads — named barriers regressed)
// + v10's psd-from-RI (no g_PSD array) + pair-local unrolled Wiener loop
// + compact PSF prep + reverse plane order + minimal syncs (S2/S5 removed).

#define MAXPLANES 12
#define INVN (1.0f / 1048576.0f)
#define PHYS(p) ((p) + (((p) >> 6) << 2))   // pad 4 float2 per 64
#define FSTR 1090                           // per-FFT smem stride; 2*FSTR%32==4

static __device__ float2 g_Z[(size_t)MAXPLANES << 20]; // 96 MB packed spectra
static __device__ float2 g_Pc[1024][32];               // compact OTF scratch
static __device__ float2 g_RI[1u << 20];               // RI filter (stored layout)
static __device__ float2 g_tw[1024];                   // W_1024^k

__device__ __forceinline__ int dr4(int i) {            // base-4 digit reversal
    unsigned x = __brev((unsigned)i) >> 22;
    return (int)(((x & 0x155u) << 1) | ((x & 0x2AAu) >> 1));
}
__device__ __forceinline__ float2 cadd(float2 a, float2 b){ return make_float2(a.x+b.x, a.y+b.y); }
__device__ __forceinline__ float2 csub(float2 a, float2 b){ return make_float2(a.x-b.x, a.y-b.y); }
__device__ __forceinline__ float2 cmul(float2 a, float2 b){ return make_float2(a.x*b.x-a.y*b.y, a.x*b.y+a.y*b.x); }
__device__ __forceinline__ float2 cmulj(float2 a, float2 w){ return make_float2(a.x*w.x+a.y*w.y, a.y*w.x-a.x*w.y); }

__device__ __forceinline__ void bf_dif(float2&x0, float2&x1, float2&x2, float2&x3, int e) {
    float2 t0=cadd(x0,x2), t1=csub(x0,x2), t2=cadd(x1,x3), t3=csub(x1,x3);
    float2 u1=make_float2(t1.x+t3.y, t1.y-t3.x);
    float2 u3=make_float2(t1.x-t3.y, t1.y+t3.x);
    x0=cadd(t0,t2);
    float2 u2=csub(t0,t2);
    x1=cmul(u1,g_tw[e]); x2=cmul(u2,g_tw[2*e]); x3=cmul(u3,g_tw[3*e]);
}
__device__ __forceinline__ void bf_dit(float2&x0, float2&x1, float2&x2, float2&x3, int e) {
    float2 a1=cmulj(x1,g_tw[e]), a2=cmulj(x2,g_tw[2*e]), a3=cmulj(x3,g_tw[3*e]);
    float2 t0=cadd(x0,a2), t1=csub(x0,a2), t2=cadd(a1,a3), t3=csub(a1,a3);
    x0=cadd(t0,t2);
    x1=make_float2(t1.x-t3.y, t1.y+t3.x);
    x2=csub(t0,t2);
    x3=make_float2(t1.x+t3.y, t1.y-t3.x);
}

__device__ __forceinline__ void dif_A(float2* x, int t) {
    #pragma unroll
    for (int k0=0;k0<4;k0++) bf_dif(x[k0],x[k0+4],x[k0+8],x[k0+12], t+64*k0);
    #pragma unroll
    for (int k0=0;k0<16;k0+=4) bf_dif(x[k0],x[k0+1],x[k0+2],x[k0+3], 4*t);
}
__device__ __forceinline__ void dif_B(float2* x, int e) {
    #pragma unroll
    for (int b=0;b<4;b++) bf_dif(x[b],x[4+b],x[8+b],x[12+b], (4*b+e)<<4);
    #pragma unroll
    for (int a=0;a<4;a++) bf_dif(x[4*a],x[4*a+1],x[4*a+2],x[4*a+3], e<<6);
}
__device__ __forceinline__ void dit_B(float2* x, int eh) {
    #pragma unroll
    for (int a=0;a<4;a++) bf_dit(x[4*a],x[4*a+1],x[4*a+2],x[4*a+3], eh<<6);
    #pragma unroll
    for (int b=0;b<4;b++) bf_dit(x[b],x[4+b],x[8+b],x[12+b], (4*b+eh)<<4);
}
__device__ __forceinline__ void dit_A(float2* x, int t) {
    #pragma unroll
    for (int k0=0;k0<16;k0+=4) bf_dit(x[k0],x[k0+1],x[k0+2],x[k0+3], t<<2);
    #pragma unroll
    for (int k0=0;k0<4;k0++) bf_dit(x[k0],x[k0+4],x[k0+8],x[k0+12], t+64*k0);
}

__device__ __forceinline__ float2 shx(float2 v, int m) {
    return make_float2(__shfl_xor_sync(0xffffffffu, v.x, m),
                       __shfl_xor_sync(0xffffffffu, v.y, m));
}
template <int M1, int M2>
__device__ __forceinline__ float2 difC(float2 v, int e) {
    float2 p = shx(v, M2);
    float2 A = ((e & 2) == 0) ? cadd(v, p) : csub(p, v);
    float2 q = shx(A, M1);
    if (e == 0) return cadd(A, q);
    if (e == 1) return csub(q, A);
    if (e == 2) return make_float2(A.x + q.y, A.y - q.x);
    return make_float2(q.x - A.y, q.y + A.x);
}
template <int M1, int M2>
__device__ __forceinline__ float2 ditC(float2 v, int e) {
    float2 p = shx(v, M2);
    float2 A = ((e & 2) == 0) ? cadd(v, p) : csub(p, v);
    float2 q = shx(A, M1);
    if (e == 0) return cadd(A, q);
    if (e == 1) return csub(q, A);
    if (e == 2) return make_float2(A.x - q.y, A.y + q.x);
    return make_float2(q.x + A.y, q.y - A.x);
}

// ---------------- init: twiddles only ------------------------------------
__global__ void k_init() {
    int idx = blockIdx.x * 256 + threadIdx.x;
    if (idx < 1024) {
        float sn, cs;
        sincospif(-(float)idx / 512.0f, &sn, &cs);
        g_tw[idx] = make_float2(cs, sn);
    }
}

// ---------------- prep: column DIF on the 32-col nonzero PSF band -------
__global__ void __launch_bounds__(512) k_colP_fast(const float* __restrict__ psf, int kh) {
    extern __shared__ float2 sb[];
    int tid = threadIdx.x;
    int f = tid & 7, t = tid >> 3;
    int m = t >> 2, e = t & 3;
    int bx = blockIdx.x;
    int c = (bx < 2) ? (bx * 8 + f) : (1008 + (bx - 2) * 8 + f);
    int cidx = c & 31;
    int kh2 = kh >> 1;
    int j = (c + kh2) & 1023;
    float2* buf = sb + f * FSTR;
    float2 x[16];
    #pragma unroll
    for (int k=0;k<16;k++) x[k] = make_float2(0.f, 0.f);
    if (j < kh) {
        int i0 = t + kh2;
        if (i0 < kh) x[0].x = psf[i0 * kh + j];
        int i15 = t - (64 - kh2);
        if (i15 >= 0) x[15].x = psf[i15 * kh + j];
    }
    dif_A(x, t);
    #pragma unroll
    for (int k=0;k<16;k++) buf[PHYS(t+64*k)] = x[k];
    __syncthreads();
    #pragma unroll
    for (int jj=0;jj<16;jj++){ int a=jj>>2,b=jj&3; x[jj]=buf[PHYS(64*m+16*a+4*b+e)]; }
    dif_B(x, e);
    int pe = ((e & 1) << 1) | ((e >> 1) & 1);
    #pragma unroll
    for (int jj=0;jj<16;jj++){
        int a=jj>>2, b=jj&3;
        g_Pc[64*m+16*a+4*b+pe][cidx] = difC<8, 16>(x[jj], e);
    }
}

// ---------------- prep: row DIF (32 nonzero cols) + RI ------------------
__global__ void __launch_bounds__(512) k_rowP_ri_fast() {
    extern __shared__ float2 sb[];
    int tid = threadIdx.x;
    int f = tid >> 6, t = tid & 63;
    int m = t >> 2, e = t & 3;
    int row = blockIdx.x * 8 + f;
    float2* buf = sb + f * FSTR;
    size_t gb = (size_t)row << 10;
    float2 x[16];
    #pragma unroll
    for (int k=0;k<16;k++) x[k] = make_float2(0.f, 0.f);
    if (t < 16) x[0]  = g_Pc[row][t];
    if (t >= 48) x[15] = g_Pc[row][(t + 960) & 31];
    dif_A(x, t);
    #pragma unroll
    for (int k=0;k<16;k++) buf[PHYS(t+64*k)] = x[k];
    __syncthreads();
    #pragma unroll
    for (int j=0;j<16;j++){ int a=j>>2,b=j&3; x[j]=buf[PHYS(64*m+16*a+4*b+e)]; }
    dif_B(x, e);
    int pe = ((e & 1) << 1) | ((e >> 1) & 1);
    #pragma unroll
    for (int j=0;j<16;j++){
        int a=j>>2, b=j&3;
        float2 h = difC<1, 2>(x[j], e);
        int P = 64*m+16*a+4*b+pe;
        float d = h.x*h.x + h.y*h.y + 0.0025f;
        float inv = 1.0f / d;
        g_RI[gb + P] = make_float2(h.x*inv, -h.y*inv);
    }
}

// ---------------- Wiener on a conjugate-mirror pair (psd from RI) --------
__device__ __forceinline__ void wiener_pair(float2 z1, float2 z2, int gi,
                                            float2& v1, float2& v2) {
    float2 za = make_float2(0.5f*(z1.x+z2.x), 0.5f*(z1.y-z2.y));
    float2 zb = make_float2(0.5f*(z1.y+z2.y), 0.5f*(z2.x-z1.x));
    float2 ri = g_RI[gi];
    float  pp = 0.0025f * (ri.x*ri.x + ri.y*ri.y) * 1048576.0f;  // sigma^2*|ri|^2*N
    float2 a = cmul(za, ri);
    float2 b = cmul(zb, ri);
    float Sa = fmaxf((a.x*a.x + a.y*a.y)*INVN - pp, 0.f);
    float Sb = fmaxf((b.x*b.x + b.y*b.y)*INVN - pp, 0.f);
    float wa = Sa / (Sa + pp + 1e-12f);
    float wb = Sb / (Sb + pp + 1e-12f);
    a.x*=wa; a.y*=wa; b.x*=wb; b.y*=wb;
    v1 = make_float2(a.x - b.y, a.y + b.x);
    v2 = make_float2(a.x + b.y, b.x - a.y);
}

// ---------------- pass 1: pack two real images, column DIF (8 cols) -----
__global__ void __launch_bounds__(512) k_col_fwd(const float* __restrict__ y) {
    extern __shared__ float2 sb[];
    int tid = threadIdx.x;
    int f = tid & 7, t = tid >> 3;
    int m = t >> 2, e = t & 3;
    size_t pb = (size_t)blockIdx.y << 20;
    const float* ya = y + (pb << 1);
    const float* yb = ya + (1u << 20);
    int c = (blockIdx.x << 3) + f;
    float2* buf = sb + f * FSTR;
    float2 x[16];
    #pragma unroll
    for (int k=0;k<16;k++){ int r=t+64*k; x[k]=make_float2(ya[(r<<10)+c], yb[(r<<10)+c]); }
    dif_A(x, t);
    #pragma unroll
    for (int k=0;k<16;k++) buf[PHYS(t+64*k)] = x[k];
    __syncthreads();
    #pragma unroll
    for (int j=0;j<16;j++){ int a=j>>2,b=j&3; x[j]=buf[PHYS(64*m+16*a+4*b+e)]; }
    dif_B(x, e);
    int pe = ((e & 1) << 1) | ((e >> 1) & 1);
    #pragma unroll
    for (int j=0;j<16;j++){
        int a=j>>2, b=j&3;
        float2 r = difC<8, 16>(x[j], e);
        g_Z[pb + ((size_t)(64*m+16*a+4*b+pe) << 10) + c] = r;
    }
}

// ---------------- pass 2: row DIF + ALIGNED Wiener + row DIT -------------
// Odd (mirror-row) slots compute conj(DIF(conj(z))): pair partner sits at the
// SAME aligned position. S2/S5 omitted (intra-quad hazards only). Block-wide
// __syncthreads (named barriers measured slower). Reverse plane order for L2.
__global__ void __launch_bounds__(256) k_row_fused() {
    __shared__ float2 sb[4 * FSTR];
    int tid = threadIdx.x;
    int f = tid >> 6, t = tid & 63;
    int m = t >> 2, e = t & 3;
    int pe = ((e & 1) << 1) | ((e >> 1) & 1);
    int pr = f >> 1, h = f & 1;                        // pair index, parity
    int bx = blockIdx.x;
    size_t pb = (size_t)(gridDim.y - 1 - blockIdx.y) << 20;   // reverse order
    int U = 2 * bx + pr;
    int row = (U == 0) ? (h ? 2 : 0) : dr4(h ? 1024 - U : U);
    bool legacy = (bx == 0 && pr == 0);                // rows {0,512}
    bool cj = (h == 1) && !legacy;                     // conjugate-trick slot
    float2* buf = sb + f * FSTR;
    size_t gbase = pb + ((size_t)row << 10);
    float2 x[16];
    #pragma unroll
    for (int k=0;k<16;k++){
        x[k] = g_Z[gbase + t + 64*k];
        if (cj) x[k].y = -x[k].y;
    }
    dif_A(x, t);
    #pragma unroll
    for (int k=0;k<16;k++) buf[PHYS(t+64*k)] = x[k];
    __syncthreads();                                   // S1
    #pragma unroll
    for (int j=0;j<16;j++){ int a=j>>2,b=j&3; x[j]=buf[PHYS(64*m+16*a+4*b+e)]; }
    dif_B(x, e);
    // no sync: C-writes hit positions whose B-readers are in-quad
    #pragma unroll
    for (int j=0;j<16;j++){
        int a=j>>2, b=j&3;
        float2 v = difC<1, 2>(x[j], e);
        if (cj) v.y = -v.y;
        buf[PHYS(64*m+16*a+4*b+pe)] = v;
    }
    __syncthreads();                                   // S3
    // ---- pair-local aligned Wiener ----
    {
        int lt = tid & 127;
        float2* ev = sb + (2*pr) * FSTR;
        float2* od = ev + FSTR;
        if (!legacy) {
            int rA = dr4(U);
            #pragma unroll
            for (int it = 0; it < 8; it++) {
                int l = lt + it * 128;
                float2 v1, v2;
                wiener_pair(ev[PHYS(l)], od[PHYS(l)], (rA << 10) + l, v1, v2);
                ev[PHYS(l)] = v1;
                od[PHYS(l)] = v2;
            }
        } else {                                       // rows {0,512}: self-mirrored
            for (int l = lt; l < 1026; l += 128) {
                int rw = (l >= 513); int cf = l - 513 * rw;
                int sc = dr4(cf), smc = dr4((1024 - cf) & 1023);
                float2 v1, v2;
                int rA = rw ? 2 : 0;
                float2* s0 = rw ? od : ev;
                wiener_pair(s0[PHYS(sc)], s0[PHYS(smc)], (rA << 10) + sc, v1, v2);
                s0[PHYS(sc)]  = v1;
                s0[PHYS(smc)] = v2;
            }
        }
    }
    __syncthreads();                                   // S4
    #pragma unroll
    for (int j=0;j<16;j++){
        int a=j>>2, b=j&3;
        float2 v = buf[PHYS(64*m+16*a+4*b+e)];
        if (cj) v.y = -v.y;
        x[j] = ditC<1, 2>(v, e);
    }
    dit_B(x, pe);
    // no sync: pe-writes hit positions whose e-readers are in-quad
    #pragma unroll
    for (int j=0;j<16;j++){ int a=j>>2,b=j&3; buf[PHYS(64*m+16*a+4*b+pe)] = x[j]; }
    __syncthreads();                                   // S6
    #pragma unroll
    for (int k=0;k<16;k++) x[k] = buf[PHYS(t+64*k)];
    dit_A(x, t);
    #pragma unroll
    for (int k=0;k<16;k++){
        float2 v = x[k];
        if (cj) v.y = -v.y;
        g_Z[gbase + t + 64*k] = v;
    }
}

// ---------------- pass 3: column DIT + unpack real/imag (8 cols) --------
__global__ void __launch_bounds__(512) k_col_inv(float* __restrict__ out) {
    extern __shared__ float2 sb[];
    int tid = threadIdx.x;
    int f = tid & 7, t = tid >> 3;
    int m = t >> 2, e = t & 3;
    size_t pb = (size_t)blockIdx.y << 20;
    float* oa = out + (pb << 1);
    float* ob = oa + (1u << 20);
    int c = (blockIdx.x << 3) + f;
    float2* buf = sb + f * FSTR;
    float2 x[16];
    #pragma unroll
    for (int j=0;j<16;j++){
        int a=j>>2, b=j&3;
        float2 v = g_Z[pb + ((size_t)(64*m+16*a+4*b+e) << 10) + c];
        x[j] = ditC<8, 16>(v, e);
    }
    int pe = ((e & 1) << 1) | ((e >> 1) & 1);
    dit_B(x, pe);
    #pragma unroll
    for (int j=0;j<16;j++){ int a=j>>2,b=j&3; buf[PHYS(64*m+16*a+4*b+pe)] = x[j]; }
    __syncthreads();
    #pragma unroll
    for (int k=0;k<16;k++) x[k] = buf[PHYS(t+64*k)];
    dit_A(x, t);
    #pragma unroll
    for (int k=0;k<16;k++){
        int r = t + 64*k;
        oa[(r<<10)+c] = x[k].x * INVN;
        ob[(r<<10)+c] = x[k].y * INVN;
    }
}

extern "C" void kernel_launch(void* const* d_in, const int* in_sizes, int n_in,
                              void* d_out, int out_size) {
    const float* y   = (const float*)d_in[0];
    const float* psf = (const float*)d_in[1];
    float* out = (float*)d_out;

    int imgs = in_sizes[0] >> 20;                      // 24
    int planes = imgs >> 1;                            // 12 packed complex planes
    if (planes > MAXPLANES) planes = MAXPLANES;
    int kh = (int)lroundf(sqrtf((float)in_sizes[1])); // 25

    const int colSmem = 8 * FSTR * (int)sizeof(float2);   // ~68 KB dynamic
    cudaFuncSetAttribute(k_colP_fast,    cudaFuncAttributeMaxDynamicSharedMemorySize, colSmem);
    cudaFuncSetAttribute(k_rowP_ri_fast, cudaFuncAttributeMaxDynamicSharedMemorySize, colSmem);
    cudaFuncSetAttribute(k_col_fwd,      cudaFuncAttributeMaxDynamicSharedMemorySize, colSmem);
    cudaFuncSetAttribute(k_col_inv,      cudaFuncAttributeMaxDynamicSharedMemorySize, colSmem);

    // OTF -> RI (compact band; stored digit-reversed layout)
    k_init<<<4, 256>>>();
    k_colP_fast<<<4, 512, colSmem>>>(psf, kh);
    k_rowP_ri_fast<<<128, 512, colSmem>>>();

    // main: col DIF -> fused(row DIF, aligned Wiener, row DIT) -> col DIT
    k_col_fwd<<<dim3(128, planes), 512, colSmem>>>(y);
    k_row_fused<<<dim3(256, planes), 256>>>();
    k_col_inv<<<dim3(128, planes), 512, colSmem>>>(out);
}